// round 14
// baseline (speedup 1.0000x reference)
#include <cuda_runtime.h>
#include <math.h>
#include <stdint.h>

// ---------------------------------------------------------------------------
// CoPE, two-kernel split:
//   K1 (gates): logits via mma.sync m16n8k16 bf16 + softmax -> g_gates (1MB)
//   K2 (expand): out = g_gates @ pos, fp32 FFMA, 8 rows/warp, shfl combine
//   inv_n = 1/max(||pos_n||,eps) folded into logits scale and gates.
// B=4, T=4096, D=4096, N=16.
// ---------------------------------------------------------------------------

#define DIM       4096
#define DIM4      1024
#define NPOS      16
#define ROWS_TOT  16384
#define ROWS_CTA  32
#define NBLOCKS   (ROWS_TOT / ROWS_CTA)   // 512
#define NTHREADS  128

// ---- kernel A (bf16 mma gates) smem ----
#define NCH1      32                      // chunks of 128 k-elems
#define QSTR      272                     // smem row stride bytes (136 bf16)
#define OFF_QB0   0                       // 32 * 272 = 8704
#define OFF_QB1   8704
#define OFF_PB0   17408                   // 16 * 272 = 4352
#define OFF_PB1   21760                   // ends 26112
#define OFF_LG    26112                   // 32*16 f32 = 2048
#define OFF_INVA  28160                   // 64 B
#define SMEM_A    28224

// ---- kernel B (expand) smem ----
#define NCH2      16
#define OFF_PF0   0                       // 16 rows * 64 f4 = 16384 B
#define OFF_PF1   16384
#define OFF_GATES 32768                   // 32*16 f32 = 2048
#define SMEM_B    34816

__device__ float g_inv[NPOS];
__device__ float g_gates[ROWS_TOT * NPOS];   // 1MB scratch (static, no alloc)

// ---------------------------------------------------------------------------
__global__ void cope_inv_kernel(const float* __restrict__ pos)
{
    const int n   = blockIdx.x;
    const int tid = threadIdx.x;
    const float* row = pos + n * DIM;
    float s = 0.f;
    #pragma unroll 4
    for (int i = tid; i < DIM; i += 256) { float v = row[i]; s = fmaf(v, v, s); }
    #pragma unroll
    for (int o = 16; o > 0; o >>= 1) s += __shfl_down_sync(0xffffffffu, s, o);
    __shared__ float sred[8];
    if ((tid & 31) == 0) sred[tid >> 5] = s;
    __syncthreads();
    if (tid == 0) {
        float t = 0.f;
        #pragma unroll
        for (int w = 0; w < 8; w++) t += sred[w];
        g_inv[n] = 1.0f / fmaxf(sqrtf(t), 1e-12f);
    }
}

// ------------------------------ helpers -----------------------------------
__device__ __forceinline__ uint32_t bf2(float lo, float hi)
{
    uint32_t r;
    asm("cvt.rn.bf16x2.f32 %0, %2, %1;" : "=r"(r) : "f"(lo), "f"(hi));
    return r;
}
__device__ __forceinline__ void cp_async16(void* s, const void* g)
{
    uint32_t sa;
    asm("{ .reg .u64 t; cvta.to.shared.u64 t, %1; cvt.u32.u64 %0, t; }"
        : "=r"(sa) : "l"(s));
    asm volatile("cp.async.cg.shared.global [%0], [%1], 16;\n" :: "r"(sa), "l"(g));
}
__device__ __forceinline__ void cp_commit() { asm volatile("cp.async.commit_group;\n" ::); }
__device__ __forceinline__ void cp_wait1()  { asm volatile("cp.async.wait_group 1;\n" ::); }
__device__ __forceinline__ void cp_wait0()  { asm volatile("cp.async.wait_group 0;\n" ::); }

__device__ __forceinline__ void mma_bf16(float* d, uint32_t a0, uint32_t a1,
                                         uint32_t a2, uint32_t a3,
                                         uint32_t b0, uint32_t b1)
{
    asm volatile("mma.sync.aligned.m16n8k16.row.col.f32.bf16.bf16.f32 "
                 "{%0,%1,%2,%3}, {%4,%5,%6,%7}, {%8,%9}, {%0,%1,%2,%3};"
                 : "+f"(d[0]), "+f"(d[1]), "+f"(d[2]), "+f"(d[3])
                 : "r"(a0), "r"(a1), "r"(a2), "r"(a3), "r"(b0), "r"(b1));
}

// ---------------------------------------------------------------------------
// kernel A staging: chunk = 128 k-elems. q: 32 rows x 32 f4; pos: 16 x 32 f4.
__device__ __forceinline__ void ldg_chunk(float4* qr, float4* pr,
                                          const float4* q4, const float4* gp4,
                                          int row0, int c, int t)
{
    const float4* src = q4 + (size_t)(row0 + (t >> 2)) * DIM4 + c * 32 + (t & 3) * 8;
    #pragma unroll
    for (int i = 0; i < 8; i++) qr[i] = src[i];
    const float4* ps = gp4 + (size_t)(t >> 3) * DIM4 + c * 32 + (t & 7) * 4;
    #pragma unroll
    for (int i = 0; i < 4; i++) pr[i] = ps[i];
}
// bf16 column offsets: 32 floats = 64 B bf16 (q), 16 floats = 32 B (pos)
__device__ __forceinline__ void sts_chunk(char* sm, const float4* qr,
                                          const float4* pr, int buf, int t)
{
    char* qb = sm + (buf ? OFF_QB1 : OFF_QB0) + (t >> 2) * QSTR + (t & 3) * 64;
    #pragma unroll
    for (int i = 0; i < 4; i++) {
        uint4 v;
        v.x = bf2(qr[2*i].x,   qr[2*i].y);   v.y = bf2(qr[2*i].z,   qr[2*i].w);
        v.z = bf2(qr[2*i+1].x, qr[2*i+1].y); v.w = bf2(qr[2*i+1].z, qr[2*i+1].w);
        *(uint4*)(qb + i * 16) = v;
    }
    char* pb = sm + (buf ? OFF_PB1 : OFF_PB0) + (t >> 3) * QSTR + (t & 7) * 32;
    #pragma unroll
    for (int i = 0; i < 2; i++) {
        uint4 v;
        v.x = bf2(pr[2*i].x,   pr[2*i].y);   v.y = bf2(pr[2*i].z,   pr[2*i].w);
        v.z = bf2(pr[2*i+1].x, pr[2*i+1].y); v.w = bf2(pr[2*i+1].z, pr[2*i+1].w);
        *(uint4*)(pb + i * 16) = v;
    }
}

// =============================== KERNEL A ==================================
__global__ void __launch_bounds__(NTHREADS, 4)
cope_gates_kernel(const float* __restrict__ q, const float* __restrict__ pos)
{
    extern __shared__ char sm[];
    float* s_lg  = (float*)(sm + OFF_LG);
    float* s_inv = (float*)(sm + OFF_INVA);

    const int tid  = threadIdx.x;
    const int wid  = tid >> 5;
    const int lane = tid & 31;
    const int row0 = blockIdx.x * ROWS_CTA;

    const float4* q4  = (const float4*)q;
    const float4* gp4 = (const float4*)pos;

    if (tid < NPOS) s_inv[tid] = g_inv[tid];

    const int mt = wid >> 1;                 // m-tile (16 rows)
    const int nh = wid & 1;                  // n-half (8 codes)
    const int r4 = lane >> 2;                // 0..7
    const int k4 = (lane & 3) * 4;           // byte offset of k pair

    float dacc[4] = {0.f, 0.f, 0.f, 0.f};
    float4 qr[8], pr[4];

    ldg_chunk(qr, pr, q4, gp4, row0, 0, tid);
    sts_chunk(sm, qr, pr, 0, tid);
    ldg_chunk(qr, pr, q4, gp4, row0, 1, tid);

    for (int c = 0; c < NCH1; c++) {
        __syncthreads();
        const char* qa = sm + ((c & 1) ? OFF_QB1 : OFF_QB0)
                         + (mt * 16 + r4) * QSTR + k4;
        const char* ba = sm + ((c & 1) ? OFF_PB1 : OFF_PB0)
                         + (nh * 8 + r4) * QSTR + k4;
        #pragma unroll
        for (int s = 0; s < 8; s++) {
            uint32_t a0 = *(const uint32_t*)(qa + s * 32);
            uint32_t a1 = *(const uint32_t*)(qa + s * 32 + 8 * QSTR);
            uint32_t a2 = *(const uint32_t*)(qa + s * 32 + 16);
            uint32_t a3 = *(const uint32_t*)(qa + s * 32 + 8 * QSTR + 16);
            uint32_t b0 = *(const uint32_t*)(ba + s * 32);
            uint32_t b1 = *(const uint32_t*)(ba + s * 32 + 16);
            mma_bf16(dacc, a0, a1, a2, a3, b0, b1);
        }
        if (c + 1 < NCH1) sts_chunk(sm, qr, pr, (c + 1) & 1, tid);
        if (c + 2 < NCH1) ldg_chunk(qr, pr, q4, gp4, row0, c + 2, tid);
    }

    // D-frag -> s_lg[32][16] (raw dots)
    {
        const int rA = mt * 16 + r4;
        const int n0 = nh * 8 + (lane & 3) * 2;
        s_lg[rA * 16 + n0]           = dacc[0];
        s_lg[rA * 16 + n0 + 1]       = dacc[1];
        s_lg[(rA + 8) * 16 + n0]     = dacc[2];
        s_lg[(rA + 8) * 16 + n0 + 1] = dacc[3];
    }
    __syncthreads();

    // softmax: one thread per row, write gates (invn folded) to gmem
    if (tid < ROWS_CTA) {
        float lg[16];
        #pragma unroll
        for (int n = 0; n < NPOS; n++)
            lg[n] = s_lg[tid * 16 + n] * 0.015625f * s_inv[n];
        float m = lg[0];
        #pragma unroll
        for (int n = 1; n < NPOS; n++) m = fmaxf(m, lg[n]);
        float e[16], sum = 0.f;
        #pragma unroll
        for (int n = 0; n < NPOS; n++) { e[n] = expf(lg[n] - m); sum += e[n]; }
        const float inv = 1.0f / sum;
        float4* gr = (float4*)(g_gates + (size_t)(row0 + tid) * NPOS);
        #pragma unroll
        for (int g4i = 0; g4i < 4; g4i++) {
            float4 v;
            v.x = e[4*g4i+0] * inv * s_inv[4*g4i+0];
            v.y = e[4*g4i+1] * inv * s_inv[4*g4i+1];
            v.z = e[4*g4i+2] * inv * s_inv[4*g4i+2];
            v.w = e[4*g4i+3] * inv * s_inv[4*g4i+3];
            gr[g4i] = v;
        }
    }
}

// =============================== KERNEL B ==================================
// pass-2 staging: chunk = 256 f32 (64 f4) per pos row
__device__ __forceinline__ void stage_pf(char* sm, int buf, const float4* gp4,
                                         int c, int tid)
{
    float4* dst = (float4*)(sm + (buf ? OFF_PF1 : OFF_PF0));
    #pragma unroll
    for (int i = 0; i < 8; i++) {
        int idx = tid + i * NTHREADS;        // 0..1023 = n*64 + d4
        int n = idx >> 6, d4 = idx & 63;
        cp_async16(dst + idx, gp4 + (size_t)n * DIM4 + c * 64 + d4);
    }
}

__global__ void __launch_bounds__(NTHREADS, 4)
cope_expand_kernel(const float* __restrict__ pos, float* __restrict__ out)
{
    extern __shared__ char sm[];
    float* s_gates = (float*)(sm + OFF_GATES);

    const int tid  = threadIdx.x;
    const int wid  = tid >> 5;               // 0..3
    const int lane = tid & 31;
    const int row0 = blockIdx.x * ROWS_CTA;

    const float4* gp4  = (const float4*)pos;
    float4*       out4 = (float4*)out;

    // stage pos chunks 0,1 + gates for this CTA's 32 rows
    stage_pf(sm, 0, gp4, 0, tid); cp_commit();
    stage_pf(sm, 1, gp4, 1, tid); cp_commit();
    ((float4*)s_gates)[tid] =
        ((const float4*)g_gates)[(size_t)row0 * 4 + tid];   // 128 f4 = 512 f
    __syncthreads();

    // warp owns 8 rows [8*wid, 8*wid+8); half h owns codes [8h, 8h+8).
    const int h  = lane >> 4;
    const int hl = lane & 15;
    const int rowb = row0 + wid * 8;

    float gt[8][8];
    #pragma unroll
    for (int i = 0; i < 8; i++) {
        const int rl = wid * 8 + ((i < 4) ? (4 * h + i) : (4 * (1 - h) + i - 4));
        const float* gb = s_gates + rl * 16 + 8 * h;
        #pragma unroll
        for (int nn = 0; nn < 8; nn++) gt[i][nn] = gb[nn];
    }

    for (int c = 0; c < NCH2; c++) {
        if (c < NCH2 - 1) cp_wait1(); else cp_wait0();
        __syncthreads();

        const float4* sp  = (const float4*)(sm + ((c & 1) ? OFF_PF1 : OFF_PF0));
        const float4* sph = sp + h * 8 * 64;

        #pragma unroll
        for (int j = 0; j < 4; j++) {
            const int d4 = hl + j * 16;
            float4 o[8];
            #pragma unroll
            for (int i = 0; i < 8; i++) o[i] = make_float4(0.f, 0.f, 0.f, 0.f);

            #pragma unroll
            for (int nn = 0; nn < 8; nn++) {
                const float4 p = sph[nn * 64 + d4];
                #pragma unroll
                for (int i = 0; i < 8; i++) {
                    o[i].x = fmaf(gt[i][nn], p.x, o[i].x);
                    o[i].y = fmaf(gt[i][nn], p.y, o[i].y);
                    o[i].z = fmaf(gt[i][nn], p.z, o[i].z);
                    o[i].w = fmaf(gt[i][nn], p.w, o[i].w);
                }
            }

            // cross-half combine: shfl partner's partials of MY rows
            #pragma unroll
            for (int i = 0; i < 4; i++) {
                float4 r;
                r.x = __shfl_xor_sync(0xffffffffu, o[4 + i].x, 16);
                r.y = __shfl_xor_sync(0xffffffffu, o[4 + i].y, 16);
                r.z = __shfl_xor_sync(0xffffffffu, o[4 + i].z, 16);
                r.w = __shfl_xor_sync(0xffffffffu, o[4 + i].w, 16);
                float4 t;
                t.x = o[i].x + r.x; t.y = o[i].y + r.y;
                t.z = o[i].z + r.z; t.w = o[i].w + r.w;
                out4[(size_t)(rowb + 4 * h + i) * DIM4 + (size_t)c * 64 + d4] = t;
            }
        }
        __syncthreads();
        if (c + 2 < NCH2) { stage_pf(sm, c & 1, gp4, c + 2, tid); cp_commit(); }
    }
}

// ---------------------------------------------------------------------------
extern "C" void kernel_launch(void* const* d_in, const int* in_sizes, int n_in,
                              void* d_out, int out_size)
{
    const float* q   = (const float*)d_in[0];
    // d_in[1] = x : unused by the reference computation
    const float* pos = (const float*)d_in[2];
    float* out = (float*)d_out;

    cudaFuncSetAttribute(cope_gates_kernel,
                         cudaFuncAttributeMaxDynamicSharedMemorySize, SMEM_A);
    cudaFuncSetAttribute(cope_expand_kernel,
                         cudaFuncAttributeMaxDynamicSharedMemorySize, SMEM_B);

    cope_inv_kernel<<<NPOS, 256>>>(pos);
    cope_gates_kernel<<<NBLOCKS, NTHREADS, SMEM_A>>>(q, pos);
    cope_expand_kernel<<<NBLOCKS, NTHREADS, SMEM_B>>>(pos, out);
}

// round 15
// speedup vs baseline: 1.8251x; 1.8251x over previous
#include <cuda_runtime.h>
#include <math.h>
#include <stdint.h>

// ---------------------------------------------------------------------------
// CoPE, f32x2 FMA, half-warp n-split, 4-buffer cp.async pipeline
// (stage-ahead 3, ONE barrier per chunk):
//   inv_n = 1/max(||pos_n||, eps)
//   logits = (q @ pos^T) * inv_n / sqrt(D); gates = softmax(logits)
//   out = (gates * inv_n) @ pos
// B=4, T=4096, D=4096, N=16.  CTA = 32 rows, 256 threads, grid = 512.
// ---------------------------------------------------------------------------

typedef unsigned long long ull;

#define DIM        4096
#define DIM4       1024               // float4 per row
#define NPOS       16
#define ROWS_TOT   16384
#define ROWS_BLK   32                 // 8 warps x 4 rows
#define NBLOCKS    (ROWS_TOT / ROWS_BLK)   // 512
#define NTHREADS   256
#define CHUNK_F4   32                 // float4 of D per row per chunk (128 f)
#define NCHUNKS    32
#define NBUF       4

#define POS_BUF_F4 (NPOS * CHUNK_F4)       // 512 f4 = 8KB
#define Q_BUF_F4   (ROWS_BLK * CHUNK_F4)   // 1024 f4 = 16KB
#define Q_BASE_F4  (NBUF * POS_BUF_F4)     // 2048
#define SMEM_BYTES ((NBUF * POS_BUF_F4 + NBUF * Q_BUF_F4) * 16)   // 96KB

__device__ float g_inv[NPOS];

// ---------------------------------------------------------------------------
__global__ void cope_inv_kernel(const float* __restrict__ pos)
{
    const int n   = blockIdx.x;
    const int tid = threadIdx.x;
    const float* row = pos + n * DIM;

    float s = 0.f;
    #pragma unroll 4
    for (int i = tid; i < DIM; i += 256) {
        float v = row[i];
        s = fmaf(v, v, s);
    }
    #pragma unroll
    for (int o = 16; o > 0; o >>= 1) s += __shfl_down_sync(0xffffffffu, s, o);

    __shared__ float sred[8];
    if ((tid & 31) == 0) sred[tid >> 5] = s;
    __syncthreads();
    if (tid == 0) {
        float t = 0.f;
        #pragma unroll
        for (int w = 0; w < 8; w++) t += sred[w];
        g_inv[n] = 1.0f / fmaxf(sqrtf(t), 1e-12f);
    }
}

// ---------------------------------------------------------------------------
__device__ __forceinline__ ull ffma2(ull a, ull b, ull c)
{
    ull d;
    asm("fma.rn.f32x2 %0, %1, %2, %3;" : "=l"(d) : "l"(a), "l"(b), "l"(c));
    return d;
}
__device__ __forceinline__ ull add2(ull a, ull b)
{
    ull d;
    asm("add.rn.f32x2 %0, %1, %2;" : "=l"(d) : "l"(a), "l"(b));
    return d;
}
__device__ __forceinline__ ull pack2(float lo, float hi)
{
    ull d;
    asm("mov.b64 %0, {%1, %2};" : "=l"(d) : "f"(lo), "f"(hi));
    return d;
}
__device__ __forceinline__ float lo2(ull a) { return __uint_as_float((unsigned)(a & 0xffffffffu)); }
__device__ __forceinline__ float hi2(ull a) { return __uint_as_float((unsigned)(a >> 32)); }

__device__ __forceinline__ void cp_async16(void* s, const void* g)
{
    uint32_t saddr;
    asm("{ .reg .u64 t; cvta.to.shared.u64 t, %1; cvt.u32.u64 %0, t; }"
        : "=r"(saddr) : "l"(s));
    asm volatile("cp.async.cg.shared.global [%0], [%1], 16;\n"
                 :: "r"(saddr), "l"(g));
}
__device__ __forceinline__ void cp_commit() { asm volatile("cp.async.commit_group;\n" ::); }
__device__ __forceinline__ void cp_wait2()  { asm volatile("cp.async.wait_group 2;\n" ::); }
__device__ __forceinline__ void cp_wait1()  { asm volatile("cp.async.wait_group 1;\n" ::); }
__device__ __forceinline__ void cp_wait0()  { asm volatile("cp.async.wait_group 0;\n" ::); }

// tail-aware wait: need chunk c; committed chunks go up to min(c+2, last)
__device__ __forceinline__ void wait_for(int lag)
{
    if (lag >= 2) cp_wait2();
    else if (lag == 1) cp_wait1();
    else cp_wait0();
}

// stage pos chunk c into buf (2 f4/thread)
__device__ __forceinline__ void stage_pos(float4* smem4, int buf,
                                          const float4* gp4, int c, int tid)
{
    float4* dst = smem4 + buf * POS_BUF_F4;
    #pragma unroll
    for (int i = 0; i < 2; i++) {
        int idx = tid + i * NTHREADS;        // 0..511
        int n = idx >> 5, d4 = idx & 31;
        cp_async16(dst + idx, gp4 + (size_t)n * DIM4 + (size_t)c * CHUNK_F4 + d4);
    }
}
// stage q chunk c into buf (4 f4/thread)
__device__ __forceinline__ void stage_q(float4* smem4, int buf,
                                        const float4* q4, int row0, int c, int tid)
{
    float4* dst = smem4 + Q_BASE_F4 + buf * Q_BUF_F4;
    #pragma unroll
    for (int i = 0; i < 4; i++) {
        int idx = tid + i * NTHREADS;        // 0..1023
        int r = idx >> 5, d4 = idx & 31;
        cp_async16(dst + idx,
                   q4 + (size_t)(row0 + r) * DIM4 + (size_t)c * CHUNK_F4 + d4);
    }
}

// ---------------------------------------------------------------------------
__global__ void __launch_bounds__(NTHREADS, 2)
cope_main_kernel(const float* __restrict__ q, const float* __restrict__ pos,
                 float* __restrict__ out)
{
    extern __shared__ float4 smem4[];

    const int tid  = threadIdx.x;
    const int wid  = tid >> 5;               // 0..7
    const int lane = tid & 31;
    const int h    = lane >> 4;              // n-half: codes [8h, 8h+8)
    const int hl   = lane & 15;              // d-slice within half
    const int row0 = blockIdx.x * ROWS_BLK;
    const int rowb = row0 + wid * 4;         // this warp's 4 rows

    const float4* q4  = (const float4*)q;
    const float4* gp4 = (const float4*)pos;
    ulonglong2*   oo  = (ulonglong2*)out;

    // prologue: stage chunks 0,1,2 (pos+q per group)
    #pragma unroll
    for (int c = 0; c < 3; c++) {
        stage_pos(smem4, c, gp4, c, tid);
        stage_q(smem4, c, q4, row0, c, tid);
        cp_commit();
    }

    // ------------------------- pass 1: logits ----------------------------
    ull acc[4][8];
    #pragma unroll
    for (int r = 0; r < 4; r++)
        #pragma unroll
        for (int nn = 0; nn < 8; nn++) acc[r][nn] = 0ull;

    for (int c = 0; c < NCHUNKS; c++) {
        wait_for(NCHUNKS - 1 - c);
        __syncthreads();                      // single barrier per chunk
        if (c + 3 < NCHUNKS) {                // stage c+3 (buf (c+3)&3 is free)
            stage_pos(smem4, (c + 3) & 3, gp4, c + 3, tid);
            stage_q(smem4, (c + 3) & 3, q4, row0, c + 3, tid);
            cp_commit();
        }

        const int b = c & 3;
        const ulonglong2* sq  = (const ulonglong2*)(smem4 + Q_BASE_F4 + b * Q_BUF_F4);
        const ulonglong2* sph = (const ulonglong2*)(smem4 + b * POS_BUF_F4)
                                + h * 8 * CHUNK_F4;

        #pragma unroll
        for (int j = 0; j < 2; j++) {
            const int d4 = hl + j * 16;
            ulonglong2 qv[4];
            #pragma unroll
            for (int r = 0; r < 4; r++)
                qv[r] = sq[(wid * 4 + r) * CHUNK_F4 + d4];

            #pragma unroll
            for (int nn = 0; nn < 8; nn++) {
                const ulonglong2 p = sph[nn * CHUNK_F4 + d4];
                #pragma unroll
                for (int r = 0; r < 4; r++) {
                    ull a = acc[r][nn];
                    a = ffma2(qv[r].x, p.x, a);
                    a = ffma2(qv[r].y, p.y, a);
                    acc[r][nn] = a;
                }
            }
        }
    }

    // prologue for pass 2: stage pos chunks 0,1,2 (bufs 0..2 provably dead)
    #pragma unroll
    for (int c = 0; c < 3; c++) {
        stage_pos(smem4, c, gp4, c, tid);
        cp_commit();
    }

    // ---- half-warp butterfly transpose-reduce over the 16 d-lanes --------
    float w[32];
    #pragma unroll
    for (int e = 0; e < 32; e++) {
        const int r  = 2 * (e >> 4) + ((e >> 3) & 1);
        const int nn = e & 7;
        w[e] = lo2(acc[r][nn]) + hi2(acc[r][nn]);
    }

#define RED_STEP(m, L)                                              \
    _Pragma("unroll")                                               \
    for (int t = 0; t < (L); t++) {                                 \
        float a_  = w[2 * t], b_ = w[2 * t + 1];                    \
        float ao_ = __shfl_xor_sync(0xffffffffu, a_, (m));          \
        float bo_ = __shfl_xor_sync(0xffffffffu, b_, (m));          \
        w[t] = (hl & (m)) ? (b_ + bo_) : (a_ + ao_);                \
    }
    RED_STEP(1, 16)
    RED_STEP(2, 8)
    RED_STEP(4, 4)
    RED_STEP(8, 2)
#undef RED_STEP

    const int  nidx = ((lane & 16) >> 1) | (lane & 7);
    const float invn = __ldg(&g_inv[nidx]);
    float lg0 = w[0] * 0.015625f * invn;
    float lg1 = w[1] * 0.015625f * invn;

    // ---- softmax over 16 codes: lane group = xor-closure of {1,2,4,16} ---
    float m0 = lg0, m1 = lg1;
    #pragma unroll
    for (int k = 0; k < 4; k++) {
        const int msk = (k < 3) ? (1 << k) : 16;
        m0 = fmaxf(m0, __shfl_xor_sync(0xffffffffu, m0, msk));
        m1 = fmaxf(m1, __shfl_xor_sync(0xffffffffu, m1, msk));
    }
    float e0 = expf(lg0 - m0), e1 = expf(lg1 - m1);
    float s0 = e0, s1 = e1;
    #pragma unroll
    for (int k = 0; k < 4; k++) {
        const int msk = (k < 3) ? (1 << k) : 16;
        s0 += __shfl_xor_sync(0xffffffffu, s0, msk);
        s1 += __shfl_xor_sync(0xffffffffu, s1, msk);
    }
    const float g0 = e0 * (1.0f / s0) * invn;
    const float g1 = e1 * (1.0f / s1) * invn;

    // gather gates for my 4 rows x my 8 codes, duplicated for f32x2
    ull gt[4][8];
    #pragma unroll
    for (int r = 0; r < 4; r++)
        #pragma unroll
        for (int nn = 0; nn < 8; nn++) {
            const int src = (lane & 16) | ((r & 1) << 3) | nn;
            float gv = __shfl_sync(0xffffffffu, (r < 2) ? g0 : g1, src);
            gt[r][nn] = pack2(gv, gv);
        }

    // -------------------------- pass 2: output ---------------------------
    for (int c = 0; c < NCHUNKS; c++) {
        wait_for(NCHUNKS - 1 - c);
        __syncthreads();
        if (c + 3 < NCHUNKS) {
            stage_pos(smem4, (c + 3) & 3, gp4, c + 3, tid);
            cp_commit();
        }

        const int b = c & 3;
        const ulonglong2* sph = (const ulonglong2*)(smem4 + b * POS_BUF_F4)
                                + h * 8 * CHUNK_F4;

        #pragma unroll
        for (int j = 0; j < 2; j++) {
            const int d4 = hl + j * 16;
            ulonglong2 o[4];
            #pragma unroll
            for (int r = 0; r < 4; r++) { o[r].x = 0ull; o[r].y = 0ull; }

            #pragma unroll
            for (int nn = 0; nn < 8; nn++) {
                const ulonglong2 p = sph[nn * CHUNK_F4 + d4];
                #pragma unroll
                for (int r = 0; r < 4; r++) {
                    o[r].x = ffma2(gt[r][nn], p.x, o[r].x);
                    o[r].y = ffma2(gt[r][nn], p.y, o[r].y);
                }
            }

            // cross-half combine: my stored rows are rowb+2h, rowb+2h+1
            ull sx0 = h ? o[0].x : o[2].x,  sy0 = h ? o[0].y : o[2].y;
            ull sx1 = h ? o[1].x : o[3].x,  sy1 = h ? o[1].y : o[3].y;
            ull rx0 = __shfl_xor_sync(0xffffffffu, sx0, 16);
            ull ry0 = __shfl_xor_sync(0xffffffffu, sy0, 16);
            ull rx1 = __shfl_xor_sync(0xffffffffu, sx1, 16);
            ull ry1 = __shfl_xor_sync(0xffffffffu, sy1, 16);

            ulonglong2 t0, t1;
            t0.x = add2(h ? o[2].x : o[0].x, rx0);
            t0.y = add2(h ? o[2].y : o[0].y, ry0);
            t1.x = add2(h ? o[3].x : o[1].x, rx1);
            t1.y = add2(h ? o[3].y : o[1].y, ry1);

            const size_t rs = (size_t)(rowb + 2 * h);
            oo[rs * DIM4 + (size_t)c * CHUNK_F4 + d4]       = t0;
            oo[(rs + 1) * DIM4 + (size_t)c * CHUNK_F4 + d4] = t1;
        }
    }
}

// ---------------------------------------------------------------------------
extern "C" void kernel_launch(void* const* d_in, const int* in_sizes, int n_in,
                              void* d_out, int out_size)
{
    const float* q   = (const float*)d_in[0];
    // d_in[1] = x : unused by the reference computation
    const float* pos = (const float*)d_in[2];
    float* out = (float*)d_out;

    cudaFuncSetAttribute(cope_main_kernel,
                         cudaFuncAttributeMaxDynamicSharedMemorySize, SMEM_BYTES);

    cope_inv_kernel<<<NPOS, 256>>>(pos);
    cope_main_kernel<<<NBLOCKS, NTHREADS, SMEM_BYTES>>>(q, pos, out);
}

// round 16
// speedup vs baseline: 1.9556x; 1.0715x over previous
#include <cuda_runtime.h>
#include <math.h>
#include <stdint.h>

// ---------------------------------------------------------------------------
// CoPE, f32x2 FMA, half-warp n-split, 4-buffer cp.async pipeline,
// unroll-4 chunk loop (compile-time buffer index) + pointer-increment staging:
//   inv_n = 1/max(||pos_n||, eps)
//   logits = (q @ pos^T) * inv_n / sqrt(D); gates = softmax(logits)
//   out = (gates * inv_n) @ pos
// B=4, T=4096, D=4096, N=16.  CTA = 32 rows, 256 threads, grid = 512.
// ---------------------------------------------------------------------------

typedef unsigned long long ull;

#define DIM        4096
#define DIM4       1024               // float4 per row
#define NPOS       16
#define ROWS_TOT   16384
#define ROWS_BLK   32                 // 8 warps x 4 rows
#define NBLOCKS    (ROWS_TOT / ROWS_BLK)   // 512
#define NTHREADS   256
#define CHUNK_F4   32                 // float4 of D per row per chunk (128 f)
#define NCHUNKS    32
#define NQUAD      (NCHUNKS / 4)      // 8

#define PBUF_B     8192               // 16 rows * 32 f4 * 16B
#define QBUF_B     16384              // 32 rows * 32 f4 * 16B
#define Q_BASE_B   (4 * PBUF_B)       // 32768
#define SMEM_BYTES (4 * PBUF_B + 4 * QBUF_B)   // 96KB -> 2 CTAs/SM

__device__ float g_inv[NPOS];

// ---------------------------------------------------------------------------
__global__ void cope_inv_kernel(const float* __restrict__ pos)
{
    const int n   = blockIdx.x;
    const int tid = threadIdx.x;
    const float* row = pos + n * DIM;

    float s = 0.f;
    #pragma unroll 4
    for (int i = tid; i < DIM; i += 256) {
        float v = row[i];
        s = fmaf(v, v, s);
    }
    #pragma unroll
    for (int o = 16; o > 0; o >>= 1) s += __shfl_down_sync(0xffffffffu, s, o);

    __shared__ float sred[8];
    if ((tid & 31) == 0) sred[tid >> 5] = s;
    __syncthreads();
    if (tid == 0) {
        float t = 0.f;
        #pragma unroll
        for (int w = 0; w < 8; w++) t += sred[w];
        g_inv[n] = 1.0f / fmaxf(sqrtf(t), 1e-12f);
    }
}

// ---------------------------------------------------------------------------
__device__ __forceinline__ ull ffma2(ull a, ull b, ull c)
{
    ull d;
    asm("fma.rn.f32x2 %0, %1, %2, %3;" : "=l"(d) : "l"(a), "l"(b), "l"(c));
    return d;
}
__device__ __forceinline__ ull add2(ull a, ull b)
{
    ull d;
    asm("add.rn.f32x2 %0, %1, %2;" : "=l"(d) : "l"(a), "l"(b));
    return d;
}
__device__ __forceinline__ ull pack2(float lo, float hi)
{
    ull d;
    asm("mov.b64 %0, {%1, %2};" : "=l"(d) : "f"(lo), "f"(hi));
    return d;
}
__device__ __forceinline__ float lo2(ull a) { return __uint_as_float((unsigned)(a & 0xffffffffu)); }
__device__ __forceinline__ float hi2(ull a) { return __uint_as_float((unsigned)(a >> 32)); }

// cp.async with precomputed shared byte address (no cvta per call)
__device__ __forceinline__ void cp_async_r(uint32_t saddr, const void* g)
{
    asm volatile("cp.async.cg.shared.global [%0], [%1], 16;\n"
                 :: "r"(saddr), "l"(g));
}
__device__ __forceinline__ void cp_commit() { asm volatile("cp.async.commit_group;\n" ::); }
__device__ __forceinline__ void cp_wait2()  { asm volatile("cp.async.wait_group 2;\n" ::); }
__device__ __forceinline__ void cp_wait1()  { asm volatile("cp.async.wait_group 1;\n" ::); }
__device__ __forceinline__ void cp_wait0()  { asm volatile("cp.async.wait_group 0;\n" ::); }

// ---------------------------------------------------------------------------
__global__ void __launch_bounds__(NTHREADS, 2)
cope_main_kernel(const float* __restrict__ q, const float* __restrict__ pos,
                 float* __restrict__ out)
{
    extern __shared__ char smc[];

    const int tid  = threadIdx.x;
    const int wid  = tid >> 5;               // 0..7
    const int lane = tid & 31;
    const int h    = lane >> 4;              // n-half: codes [8h, 8h+8)
    const int hl   = lane & 15;              // d-slice within half
    const int row0 = blockIdx.x * ROWS_BLK;
    const int rowb = row0 + wid * 4;         // this warp's 4 rows

    const float4* q4  = (const float4*)q;
    const float4* gp4 = (const float4*)pos;
    ulonglong2*   oo  = (ulonglong2*)out;

    // ---- staging state: 1 cvta, pointer-increment global sources ---------
    uint32_t smb;
    asm("{ .reg .u64 t; cvta.to.shared.u64 t, %1; cvt.u32.u64 %0, t; }"
        : "=r"(smb) : "l"(smc));
    const uint32_t sp0 = smb + tid * 16;                 // pos slot, buf 0
    const uint32_t sq0 = smb + Q_BASE_B + tid * 16;      // q slot, buf 0
    const float4* gq = q4 + (size_t)(row0 + (tid >> 5)) * DIM4 + (tid & 31);
    const float4* gp = gp4 + (size_t)(tid >> 5) * DIM4 + (tid & 31);

    // slot i offsets: smem +4096*i bytes; gmem +8*DIM4*i float4 (const!)
#define STAGE_POS(BUF) do {                                             \
        cp_async_r(sp0 + (BUF) * PBUF_B,        gp);                    \
        cp_async_r(sp0 + (BUF) * PBUF_B + 4096, gp + 8 * DIM4);         \
    } while (0)
#define STAGE_Q(BUF) do {                                               \
        cp_async_r(sq0 + (BUF) * QBUF_B,         gq);                   \
        cp_async_r(sq0 + (BUF) * QBUF_B + 4096,  gq + 8  * DIM4);       \
        cp_async_r(sq0 + (BUF) * QBUF_B + 8192,  gq + 16 * DIM4);       \
        cp_async_r(sq0 + (BUF) * QBUF_B + 12288, gq + 24 * DIM4);       \
    } while (0)

    // prologue: stage chunks 0,1,2
    STAGE_POS(0); STAGE_Q(0); cp_commit(); gp += CHUNK_F4; gq += CHUNK_F4;
    STAGE_POS(1); STAGE_Q(1); cp_commit(); gp += CHUNK_F4; gq += CHUNK_F4;
    STAGE_POS(2); STAGE_Q(2); cp_commit(); gp += CHUNK_F4; gq += CHUNK_F4;

    // ------------------------- pass 1: logits ----------------------------
    ull acc[4][8];
    #pragma unroll
    for (int r = 0; r < 4; r++)
        #pragma unroll
        for (int nn = 0; nn < 8; nn++) acc[r][nn] = 0ull;

    for (int cq = 0; cq < NQUAD; cq++) {
        const bool last = (cq == NQUAD - 1);
        #pragma unroll
        for (int u = 0; u < 4; u++) {        // c = 4*cq + u, buf = u
            // tail-aware wait (u compile-time)
            if (u <= 1)      cp_wait2();
            else if (u == 2) { if (last) cp_wait1(); else cp_wait2(); }
            else             { if (last) cp_wait0(); else cp_wait2(); }
            __syncthreads();                 // single barrier per chunk

            if (!last || u == 0) {           // stage chunk c+3 into buf (u+3)&3
                STAGE_POS((u + 3) & 3); STAGE_Q((u + 3) & 3); cp_commit();
                gp += CHUNK_F4; gq += CHUNK_F4;
            }

            const ulonglong2* sq  =
                (const ulonglong2*)(smc + Q_BASE_B + u * QBUF_B);
            const ulonglong2* sph =
                (const ulonglong2*)(smc + u * PBUF_B) + h * 8 * CHUNK_F4;

            #pragma unroll
            for (int j = 0; j < 2; j++) {
                const int d4 = hl + j * 16;
                ulonglong2 qv[4];
                #pragma unroll
                for (int r = 0; r < 4; r++)
                    qv[r] = sq[(wid * 4 + r) * CHUNK_F4 + d4];

                #pragma unroll
                for (int nn = 0; nn < 8; nn++) {
                    const ulonglong2 p = sph[nn * CHUNK_F4 + d4];
                    #pragma unroll
                    for (int r = 0; r < 4; r++) {
                        ull a = acc[r][nn];
                        a = ffma2(qv[r].x, p.x, a);
                        a = ffma2(qv[r].y, p.y, a);
                        acc[r][nn] = a;
                    }
                }
            }
        }
    }

    // prologue for pass 2: rewind pos, stage chunks 0,1,2 (bufs 0..2 dead)
    gp -= NCHUNKS * CHUNK_F4;
    STAGE_POS(0); cp_commit(); gp += CHUNK_F4;
    STAGE_POS(1); cp_commit(); gp += CHUNK_F4;
    STAGE_POS(2); cp_commit(); gp += CHUNK_F4;

    // ---- half-warp butterfly transpose-reduce over the 16 d-lanes --------
    float w[32];
    #pragma unroll
    for (int e = 0; e < 32; e++) {
        const int r  = 2 * (e >> 4) + ((e >> 3) & 1);
        const int nn = e & 7;
        w[e] = lo2(acc[r][nn]) + hi2(acc[r][nn]);
    }

#define RED_STEP(m, L)                                              \
    _Pragma("unroll")                                               \
    for (int t = 0; t < (L); t++) {                                 \
        float a_  = w[2 * t], b_ = w[2 * t + 1];                    \
        float ao_ = __shfl_xor_sync(0xffffffffu, a_, (m));          \
        float bo_ = __shfl_xor_sync(0xffffffffu, b_, (m));          \
        w[t] = (hl & (m)) ? (b_ + bo_) : (a_ + ao_);                \
    }
    RED_STEP(1, 16)
    RED_STEP(2, 8)
    RED_STEP(4, 4)
    RED_STEP(8, 2)
#undef RED_STEP

    const int  nidx = ((lane & 16) >> 1) | (lane & 7);
    const float invn = __ldg(&g_inv[nidx]);
    float lg0 = w[0] * 0.015625f * invn;
    float lg1 = w[1] * 0.015625f * invn;

    // ---- softmax over 16 codes: lane group = xor-closure of {1,2,4,16} ---
    float m0 = lg0, m1 = lg1;
    #pragma unroll
    for (int k = 0; k < 4; k++) {
        const int msk = (k < 3) ? (1 << k) : 16;
        m0 = fmaxf(m0, __shfl_xor_sync(0xffffffffu, m0, msk));
        m1 = fmaxf(m1, __shfl_xor_sync(0xffffffffu, m1, msk));
    }
    float e0 = expf(lg0 - m0), e1 = expf(lg1 - m1);
    float s0 = e0, s1 = e1;
    #pragma unroll
    for (int k = 0; k < 4; k++) {
        const int msk = (k < 3) ? (1 << k) : 16;
        s0 += __shfl_xor_sync(0xffffffffu, s0, msk);
        s1 += __shfl_xor_sync(0xffffffffu, s1, msk);
    }
    const float g0 = e0 * (1.0f / s0) * invn;
    const float g1 = e1 * (1.0f / s1) * invn;

    // gather gates for my 4 rows x my 8 codes, duplicated for f32x2
    ull gt[4][8];
    #pragma unroll
    for (int r = 0; r < 4; r++)
        #pragma unroll
        for (int nn = 0; nn < 8; nn++) {
            const int src = (lane & 16) | ((r & 1) << 3) | nn;
            float gv = __shfl_sync(0xffffffffu, (r < 2) ? g0 : g1, src);
            gt[r][nn] = pack2(gv, gv);
        }

    // -------------------------- pass 2: output ---------------------------
    for (int cq = 0; cq < NQUAD; cq++) {
        const bool last = (cq == NQUAD - 1);
        #pragma unroll
        for (int u = 0; u < 4; u++) {        // c = 4*cq + u, buf = u
            if (u <= 1)      cp_wait2();
            else if (u == 2) { if (last) cp_wait1(); else cp_wait2(); }
            else             { if (last) cp_wait0(); else cp_wait2(); }
            __syncthreads();

            if (!last || u == 0) {
                STAGE_POS((u + 3) & 3); cp_commit();
                gp += CHUNK_F4;
            }

            const int c = cq * 4 + u;
            const ulonglong2* sph =
                (const ulonglong2*)(smc + u * PBUF_B) + h * 8 * CHUNK_F4;

            #pragma unroll
            for (int j = 0; j < 2; j++) {
                const int d4 = hl + j * 16;
                ulonglong2 o[4];
                #pragma unroll
                for (int r = 0; r < 4; r++) { o[r].x = 0ull; o[r].y = 0ull; }

                #pragma unroll
                for (int nn = 0; nn < 8; nn++) {
                    const ulonglong2 p = sph[nn * CHUNK_F4 + d4];
                    #pragma unroll
                    for (int r = 0; r < 4; r++) {
                        o[r].x = ffma2(gt[r][nn], p.x, o[r].x);
                        o[r].y = ffma2(gt[r][nn], p.y, o[r].y);
                    }
                }

                // cross-half combine: my stored rows are rowb+2h, rowb+2h+1
                ull sx0 = h ? o[0].x : o[2].x,  sy0 = h ? o[0].y : o[2].y;
                ull sx1 = h ? o[1].x : o[3].x,  sy1 = h ? o[1].y : o[3].y;
                ull rx0 = __shfl_xor_sync(0xffffffffu, sx0, 16);
                ull ry0 = __shfl_xor_sync(0xffffffffu, sy0, 16);
                ull rx1 = __shfl_xor_sync(0xffffffffu, sx1, 16);
                ull ry1 = __shfl_xor_sync(0xffffffffu, sy1, 16);

                ulonglong2 t0, t1;
                t0.x = add2(h ? o[2].x : o[0].x, rx0);
                t0.y = add2(h ? o[2].y : o[0].y, ry0);
                t1.x = add2(h ? o[3].x : o[1].x, rx1);
                t1.y = add2(h ? o[3].y : o[1].y, ry1);

                const size_t rs = (size_t)(rowb + 2 * h);
                oo[rs * DIM4 + (size_t)c * CHUNK_F4 + d4]       = t0;
                oo[(rs + 1) * DIM4 + (size_t)c * CHUNK_F4 + d4] = t1;
            }
        }
    }
}

// ---------------------------------------------------------------------------
extern "C" void kernel_launch(void* const* d_in, const int* in_sizes, int n_in,
                              void* d_out, int out_size)
{
    const float* q   = (const float*)d_in[0];
    // d_in[1] = x : unused by the reference computation
    const float* pos = (const float*)d_in[2];
    float* out = (float*)d_out;

    cudaFuncSetAttribute(cope_main_kernel,
                         cudaFuncAttributeMaxDynamicSharedMemorySize, SMEM_BYTES);

    cope_inv_kernel<<<NPOS, 256>>>(pos);
    cope_main_kernel<<<NBLOCKS, NTHREADS, SMEM_BYTES>>>(q, pos, out);
}